// round 2
// baseline (speedup 1.0000x reference)
#include <cuda_runtime.h>

// Problem shapes (fixed for this dataset entry)
#define B_   4
#define Q_   128
#define N_   50000
#define C_   20
#define BQ_  (B_ * Q_)          // 512
#define BN_  (B_ * N_)          // 200000
#define NV_  (N_ / 4)           // 12500 float4 per row

#define MIN_PTS_NUM  50
#define MIN_INST_CLS 4

// Output layout (fp32 concatenation, matching reference return order)
#define OFF_MASKS  0
#define OFF_SCORES ((size_t)BQ_ * N_)            // 25,600,000
#define OFF_VALID  (OFF_SCORES + BQ_)            // 25,600,512
#define OFF_CLS    (OFF_VALID + BQ_)             // 25,601,024
#define OFF_GID    (OFF_CLS + BQ_)               // 25,601,536

// Scratch (no device allocation allowed -> __device__ globals)
__device__ int           g_cls_pred[BQ_];
__device__ int           g_valid[BQ_];
__device__ unsigned char g_seg8[BN_];

// ---------------------------------------------------------------------------
// Kernel 1: convert seg_pred (int32, values 0..19) to uint8, and compute
// per-(b,q) class argmax over C=20 logits.
// ---------------------------------------------------------------------------
__global__ __launch_bounds__(256)
void prep_kernel(const float* __restrict__ cls_logits,
                 const int* __restrict__ seg_pred,
                 float* __restrict__ out_cls)
{
    int i = blockIdx.x * blockDim.x + threadIdx.x;
    int stride = gridDim.x * blockDim.x;
    for (int j = i; j < BN_; j += stride)
        g_seg8[j] = (unsigned char)seg_pred[j];

    if (i < BQ_) {
        const float* p = cls_logits + i * C_;
        float best = p[0];
        int bi = 0;
        #pragma unroll
        for (int c = 1; c < C_; c++) {
            float v = p[c];
            if (v > best) { best = v; bi = c; }   // first-max, matches jnp.argmax
        }
        g_cls_pred[i] = bi;
        out_cls[i] = (float)bi;
    }
}

// ---------------------------------------------------------------------------
// Kernel 2: one block per (b,q). Streams the N=50000 logits row as float4 and
// the seg row as uchar4. Writes sel (pre-valid) as float mask, block-reduces
// (count, sum of sigmoid over selected), writes score/valid.
// sigmoid(x) > 0.5  <=>  x > 0, so no MUFU for selection; sigmoid only where
// selected (~2.5% of points).
// ---------------------------------------------------------------------------
__global__ __launch_bounds__(256)
void mask_reduce_kernel(const float* __restrict__ mask_logits,
                        float* __restrict__ out_masks,
                        float* __restrict__ out_scores,
                        float* __restrict__ out_valid)
{
    const int bq  = blockIdx.x;
    const int b   = bq / Q_;
    const int cls = g_cls_pred[bq];

    const float4* __restrict__ ml = reinterpret_cast<const float4*>(mask_logits + (size_t)bq * N_);
    const uchar4* __restrict__ sp = reinterpret_cast<const uchar4*>(g_seg8 + (size_t)b * N_);
    float4* __restrict__ om       = reinterpret_cast<float4*>(out_masks + (size_t)bq * N_);

    int   cnt  = 0;
    float ssum = 0.f;

    for (int i = threadIdx.x; i < NV_; i += 256) {
        float4 x = ml[i];
        uchar4 s = sp[i];
        bool s0 = (x.x > 0.f) & ((int)s.x == cls);
        bool s1 = (x.y > 0.f) & ((int)s.y == cls);
        bool s2 = (x.z > 0.f) & ((int)s.z == cls);
        bool s3 = (x.w > 0.f) & ((int)s.w == cls);
        float4 o;
        o.x = s0 ? 1.f : 0.f;
        o.y = s1 ? 1.f : 0.f;
        o.z = s2 ? 1.f : 0.f;
        o.w = s3 ? 1.f : 0.f;
        cnt += (int)s0 + (int)s1 + (int)s2 + (int)s3;
        if (s0 | s1 | s2 | s3) {
            if (s0) ssum += __fdividef(1.f, 1.f + __expf(-x.x));
            if (s1) ssum += __fdividef(1.f, 1.f + __expf(-x.y));
            if (s2) ssum += __fdividef(1.f, 1.f + __expf(-x.z));
            if (s3) ssum += __fdividef(1.f, 1.f + __expf(-x.w));
        }
        om[i] = o;
    }

    // Block reduction (256 threads = 8 warps)
    __shared__ int   scnt[8];
    __shared__ float ssumsh[8];
    #pragma unroll
    for (int off = 16; off > 0; off >>= 1) {
        cnt  += __shfl_down_sync(0xFFFFFFFFu, cnt,  off);
        ssum += __shfl_down_sync(0xFFFFFFFFu, ssum, off);
    }
    int wid  = threadIdx.x >> 5;
    int lane = threadIdx.x & 31;
    if (lane == 0) { scnt[wid] = cnt; ssumsh[wid] = ssum; }
    __syncthreads();

    if (threadIdx.x == 0) {
        int   tc = 0;
        float ts = 0.f;
        #pragma unroll
        for (int w = 0; w < 8; w++) { tc += scnt[w]; ts += ssumsh[w]; }
        int v = (tc >= MIN_PTS_NUM) && (cls >= MIN_INST_CLS);
        g_valid[bq]    = v;
        out_valid[bq]  = (float)v;
        out_scores[bq] = v ? ts / (float)(tc > 1 ? tc : 1) : 0.f;
    }
}

// ---------------------------------------------------------------------------
// Kernel 3: zero mask rows whose query is invalid (sel & valid).
// ---------------------------------------------------------------------------
__global__ __launch_bounds__(256)
void zero_invalid_kernel(float* __restrict__ out_masks)
{
    const int bq = blockIdx.x;
    if (g_valid[bq]) return;
    float4* __restrict__ om = reinterpret_cast<float4*>(out_masks + (size_t)bq * N_);
    float4 z = make_float4(0.f, 0.f, 0.f, 0.f);
    for (int i = threadIdx.x; i < NV_; i += 256)
        om[i] = z;
}

// ---------------------------------------------------------------------------
// Kernel 4: global_ids = fg_idxs as float (values < 300000 < 2^24, exact).
// ---------------------------------------------------------------------------
__global__ __launch_bounds__(256)
void gid_kernel(const int* __restrict__ fg_idxs,
                float* __restrict__ out_gid)
{
    int i = blockIdx.x * blockDim.x + threadIdx.x;
    if (i < BN_) out_gid[i] = (float)fg_idxs[i];
}

// ---------------------------------------------------------------------------
extern "C" void kernel_launch(void* const* d_in, const int* in_sizes, int n_in,
                              void* d_out, int out_size)
{
    const float* mask_logits = (const float*)d_in[0];   // [B,Q,N]  fp32
    const float* cls_logits  = (const float*)d_in[1];   // [B,Q,C]  fp32
    const int*   seg_pred    = (const int*)d_in[2];     // [B,N]    int32 (JAX x64 off)
    const int*   fg_idxs     = (const int*)d_in[3];     // [B*N]    int32
    float* out = (float*)d_out;

    float* out_masks  = out + OFF_MASKS;
    float* out_scores = out + OFF_SCORES;
    float* out_valid  = out + OFF_VALID;
    float* out_cls    = out + OFF_CLS;
    float* out_gid    = out + OFF_GID;

    prep_kernel<<<(BN_ + 255) / 256, 256>>>(cls_logits, seg_pred, out_cls);
    mask_reduce_kernel<<<BQ_, 256>>>(mask_logits, out_masks, out_scores, out_valid);
    zero_invalid_kernel<<<BQ_, 256>>>(out_masks);
    gid_kernel<<<(BN_ + 255) / 256, 256>>>(fg_idxs, out_gid);
}

// round 3
// speedup vs baseline: 2.1115x; 2.1115x over previous
#include <cuda_runtime.h>

// Problem shapes (fixed for this dataset entry)
#define B_   4
#define Q_   128
#define N_   50000
#define C_   20
#define BQ_  (B_ * Q_)          // 512
#define BN_  (B_ * N_)          // 200000
#define NV_  (N_ / 4)           // 12500 float4 per row
#define S_   10                 // chunks per row
#define CHUNK_ (NV_ / S_)       // 1250 float4 per chunk

#define MIN_PTS_NUM  50
#define MIN_INST_CLS 4
#define FIXSCALE 16777216.0f    // 2^24 fixed-point for deterministic sigmoid sum

// Output layout (fp32 concatenation, matching reference return order)
#define OFF_SCORES ((size_t)BQ_ * N_)            // 25,600,000
#define OFF_VALID  (OFF_SCORES + BQ_)
#define OFF_CLS    (OFF_VALID + BQ_)
#define OFF_GID    (OFF_CLS + BQ_)

// Scratch (no device allocation allowed -> __device__ globals)
__device__ int                g_cls_pred[BQ_];
__device__ int                g_cnt[BQ_];
__device__ unsigned long long g_ssum[BQ_];
__device__ unsigned char      g_seg8[BN_];

// ---------------------------------------------------------------------------
// Kernel 1: seg int32 -> uint8 repack, fg_idxs -> float, per-(b,q) argmax,
// scratch reset. All small-stuff fused.
// ---------------------------------------------------------------------------
__global__ __launch_bounds__(256)
void prep_kernel(const float* __restrict__ cls_logits,
                 const int* __restrict__ seg_pred,
                 const int* __restrict__ fg_idxs,
                 float* __restrict__ out_cls,
                 float* __restrict__ out_gid)
{
    int i = blockIdx.x * blockDim.x + threadIdx.x;
    if (i < BN_) {
        g_seg8[i]  = (unsigned char)seg_pred[i];
        out_gid[i] = (float)fg_idxs[i];
    }
    if (i < BQ_) {
        const float* p = cls_logits + i * C_;
        float best = p[0];
        int bi = 0;
        #pragma unroll
        for (int c = 1; c < C_; c++) {
            float v = p[c];
            if (v > best) { best = v; bi = c; }   // first-max, matches jnp.argmax
        }
        g_cls_pred[i] = bi;
        out_cls[i] = (float)bi;
        g_cnt[i]   = 0;
        g_ssum[i]  = 0ULL;
    }
}

// ---------------------------------------------------------------------------
// Kernel 2: grid (S_, BQ_). Each block handles one 1250-float4 chunk of one
// (b,q) row. cls<4 rows are invalid regardless of count -> stream zeros, no
// logit read. Otherwise: sel = (logit>0) & (seg==cls); write mask; block-
// reduce (count, fixed-point sigmoid sum); one atomic pair per block.
// sigmoid(x)>0.5 <=> x>0 so selection needs no MUFU.
// ---------------------------------------------------------------------------
__global__ __launch_bounds__(256)
void mask_chunk_kernel(const float* __restrict__ mask_logits,
                       float* __restrict__ out_masks)
{
    const int chunk = blockIdx.x;
    const int bq    = blockIdx.y;
    const int b     = bq >> 7;            // / Q_
    const int cls   = g_cls_pred[bq];
    const size_t base = (size_t)bq * NV_ + (size_t)chunk * CHUNK_;

    float4* __restrict__ om = reinterpret_cast<float4*>(out_masks) + base;

    if (cls < MIN_INST_CLS) {
        const float4 z = make_float4(0.f, 0.f, 0.f, 0.f);
        #pragma unroll
        for (int k = 0; k < 5; k++) {
            int i = threadIdx.x + k * 256;
            if (i < CHUNK_) om[i] = z;
        }
        return;
    }

    const float4* __restrict__ ml = reinterpret_cast<const float4*>(mask_logits) + base;
    const uchar4* __restrict__ sp = reinterpret_cast<const uchar4*>(g_seg8) +
                                    (size_t)b * NV_ + (size_t)chunk * CHUNK_;

    int   cnt  = 0;
    float ssum = 0.f;

    // Fully unrolled: 5 independent (float4, uchar4) load pairs batched up
    // front for MLP, then compute+store.
    float4 x[5]; uchar4 s[5]; bool ok[5];
    #pragma unroll
    for (int k = 0; k < 5; k++) {
        int i = threadIdx.x + k * 256;
        ok[k] = (i < CHUNK_);
        if (ok[k]) { x[k] = ml[i]; s[k] = sp[i]; }
    }
    #pragma unroll
    for (int k = 0; k < 5; k++) {
        if (!ok[k]) continue;
        int i = threadIdx.x + k * 256;
        bool s0 = (x[k].x > 0.f) & ((int)s[k].x == cls);
        bool s1 = (x[k].y > 0.f) & ((int)s[k].y == cls);
        bool s2 = (x[k].z > 0.f) & ((int)s[k].z == cls);
        bool s3 = (x[k].w > 0.f) & ((int)s[k].w == cls);
        float4 o;
        o.x = s0 ? 1.f : 0.f;
        o.y = s1 ? 1.f : 0.f;
        o.z = s2 ? 1.f : 0.f;
        o.w = s3 ? 1.f : 0.f;
        om[i] = o;
        cnt += (int)s0 + (int)s1 + (int)s2 + (int)s3;
        if (s0 | s1 | s2 | s3) {
            if (s0) ssum += __fdividef(1.f, 1.f + __expf(-x[k].x));
            if (s1) ssum += __fdividef(1.f, 1.f + __expf(-x[k].y));
            if (s2) ssum += __fdividef(1.f, 1.f + __expf(-x[k].z));
            if (s3) ssum += __fdividef(1.f, 1.f + __expf(-x[k].w));
        }
    }

    // Deterministic fixed-point conversion before reduction
    unsigned long long fsum = (unsigned long long)(ssum * FIXSCALE + 0.5f);

    // Block reduction (8 warps)
    __shared__ int                scnt[8];
    __shared__ unsigned long long ssh[8];
    #pragma unroll
    for (int off = 16; off > 0; off >>= 1) {
        cnt  += __shfl_down_sync(0xFFFFFFFFu, cnt,  off);
        fsum += __shfl_down_sync(0xFFFFFFFFu, fsum, off);
    }
    int wid  = threadIdx.x >> 5;
    int lane = threadIdx.x & 31;
    if (lane == 0) { scnt[wid] = cnt; ssh[wid] = fsum; }
    __syncthreads();
    if (threadIdx.x == 0) {
        int tc = 0; unsigned long long ts = 0ULL;
        #pragma unroll
        for (int w = 0; w < 8; w++) { tc += scnt[w]; ts += ssh[w]; }
        atomicAdd(&g_cnt[bq], tc);
        atomicAdd(&g_ssum[bq], ts);
    }
}

// ---------------------------------------------------------------------------
// Kernel 3: grid (S_, BQ_). Emit score/valid; re-zero the (rare) rows that
// have cls>=4 but cnt<50. cls<4 rows were already zero-streamed in K2.
// ---------------------------------------------------------------------------
__global__ __launch_bounds__(256)
void finalize_kernel(float* __restrict__ out_masks,
                     float* __restrict__ out_scores,
                     float* __restrict__ out_valid)
{
    const int chunk = blockIdx.x;
    const int bq    = blockIdx.y;
    const int cls   = g_cls_pred[bq];
    const int cnt   = g_cnt[bq];
    const int v     = (cnt >= MIN_PTS_NUM) && (cls >= MIN_INST_CLS);

    if (chunk == 0 && threadIdx.x == 0) {
        out_valid[bq] = (float)v;
        float sum = (float)((double)g_ssum[bq] * (1.0 / 16777216.0));
        out_scores[bq] = v ? sum / (float)cnt : 0.f;
    }

    if (!v && cls >= MIN_INST_CLS) {   // rare: big class but too few points
        float4* __restrict__ om = reinterpret_cast<float4*>(out_masks) +
                                  (size_t)bq * NV_ + (size_t)chunk * CHUNK_;
        const float4 z = make_float4(0.f, 0.f, 0.f, 0.f);
        #pragma unroll
        for (int k = 0; k < 5; k++) {
            int i = threadIdx.x + k * 256;
            if (i < CHUNK_) om[i] = z;
        }
    }
}

// ---------------------------------------------------------------------------
extern "C" void kernel_launch(void* const* d_in, const int* in_sizes, int n_in,
                              void* d_out, int out_size)
{
    const float* mask_logits = (const float*)d_in[0];   // [B,Q,N]  fp32
    const float* cls_logits  = (const float*)d_in[1];   // [B,Q,C]  fp32
    const int*   seg_pred    = (const int*)d_in[2];     // [B,N]    int32
    const int*   fg_idxs     = (const int*)d_in[3];     // [B*N]    int32
    float* out = (float*)d_out;

    float* out_masks  = out;
    float* out_scores = out + OFF_SCORES;
    float* out_valid  = out + OFF_VALID;
    float* out_cls    = out + OFF_CLS;
    float* out_gid    = out + OFF_GID;

    dim3 grid2(S_, BQ_);
    prep_kernel<<<(BN_ + 255) / 256, 256>>>(cls_logits, seg_pred, fg_idxs,
                                            out_cls, out_gid);
    mask_chunk_kernel<<<grid2, 256>>>(mask_logits, out_masks);
    finalize_kernel<<<grid2, 256>>>(out_masks, out_scores, out_valid);
}

// round 4
// speedup vs baseline: 2.2006x; 1.0422x over previous
#include <cuda_runtime.h>

// Problem shapes (fixed for this dataset entry)
#define B_   4
#define Q_   128
#define N_   50000
#define C_   20
#define BQ_  (B_ * Q_)          // 512
#define BN_  (B_ * N_)          // 200000
#define NV_  (N_ / 4)           // 12500 float4 per row
#define S_   10                 // chunks per row
#define CHUNK_ (NV_ / S_)       // 1250 float4 per chunk

#define MIN_PTS_NUM  50
#define MIN_INST_CLS 4
#define FIXSCALE 16777216.0f    // 2^24 fixed-point for deterministic sigmoid sum

// Output layout (fp32 concatenation, matching reference return order)
#define OFF_SCORES ((size_t)BQ_ * N_)            // 25,600,000
#define OFF_VALID  (OFF_SCORES + BQ_)
#define OFF_CLS    (OFF_VALID + BQ_)
#define OFF_GID    (OFF_CLS + BQ_)

// Scratch (no device allocation allowed -> __device__ globals)
__device__ int                g_cls_pred[BQ_];
__device__ int                g_cnt[BQ_];
__device__ unsigned long long g_ssum[BQ_];

// ---------------------------------------------------------------------------
// Kernel 1 (prep-lite, 2 blocks): per-(b,q) argmax over C=20, out_cls write,
// and counter reset. Resetting HERE (start of each invocation) makes graph
// replays self-consistent with no finalize-side race.
// ---------------------------------------------------------------------------
__global__ __launch_bounds__(256)
void prep_lite_kernel(const float* __restrict__ cls_logits,
                      float* __restrict__ out_cls)
{
    int i = blockIdx.x * blockDim.x + threadIdx.x;
    if (i < BQ_) {
        const float* p = cls_logits + i * C_;
        float best = p[0];
        int bi = 0;
        #pragma unroll
        for (int c = 1; c < C_; c++) {
            float v = p[c];
            if (v > best) { best = v; bi = c; }   // first-max, matches jnp.argmax
        }
        g_cls_pred[i] = bi;
        out_cls[i] = (float)bi;
        g_cnt[i]   = 0;
        g_ssum[i]  = 0ULL;
    }
}

// ---------------------------------------------------------------------------
// Kernel 2: grid (S_, BQ_). One block per 1250-float4 chunk of one (b,q) row.
// cls<4 rows are invalid regardless of count -> stream zeros, no logit read.
// seg_pred is read as int4 directly (800KB total, L2-resident across the 128
// queries that reuse each batch row). Logit reads/mask writes use streaming
// cache hints to keep L2 for seg reuse.
// sigmoid(x)>0.5 <=> x>0 so selection needs no MUFU.
// ---------------------------------------------------------------------------
__global__ __launch_bounds__(256)
void mask_chunk_kernel(const float* __restrict__ mask_logits,
                       const int* __restrict__ seg_pred,
                       float* __restrict__ out_masks)
{
    const int chunk = blockIdx.x;
    const int bq    = blockIdx.y;
    const int b     = bq >> 7;            // / Q_
    const int cls   = g_cls_pred[bq];     // broadcast load
    const size_t base = (size_t)bq * NV_ + (size_t)chunk * CHUNK_;

    float4* __restrict__ om = reinterpret_cast<float4*>(out_masks) + base;

    if (cls < MIN_INST_CLS) {
        const float4 z = make_float4(0.f, 0.f, 0.f, 0.f);
        #pragma unroll
        for (int k = 0; k < 5; k++) {
            int i = threadIdx.x + k * 256;
            if (i < CHUNK_) __stcs(&om[i], z);
        }
        return;
    }

    const float4* __restrict__ ml = reinterpret_cast<const float4*>(mask_logits) + base;
    const int4*   __restrict__ sp = reinterpret_cast<const int4*>(seg_pred) +
                                    (size_t)b * NV_ + (size_t)chunk * CHUNK_;

    int   cnt  = 0;
    float ssum = 0.f;

    // Fully unrolled: 5 independent (float4, int4) load pairs batched up
    // front for MLP, then compute+store.
    float4 x[5]; int4 s[5]; bool ok[5];
    #pragma unroll
    for (int k = 0; k < 5; k++) {
        int i = threadIdx.x + k * 256;
        ok[k] = (i < CHUNK_);
        if (ok[k]) { x[k] = __ldcs(&ml[i]); s[k] = __ldg(&sp[i]); }
    }
    #pragma unroll
    for (int k = 0; k < 5; k++) {
        if (!ok[k]) continue;
        int i = threadIdx.x + k * 256;
        bool s0 = (x[k].x > 0.f) & (s[k].x == cls);
        bool s1 = (x[k].y > 0.f) & (s[k].y == cls);
        bool s2 = (x[k].z > 0.f) & (s[k].z == cls);
        bool s3 = (x[k].w > 0.f) & (s[k].w == cls);
        float4 o;
        o.x = s0 ? 1.f : 0.f;
        o.y = s1 ? 1.f : 0.f;
        o.z = s2 ? 1.f : 0.f;
        o.w = s3 ? 1.f : 0.f;
        __stcs(&om[i], o);
        cnt += (int)s0 + (int)s1 + (int)s2 + (int)s3;
        if (s0 | s1 | s2 | s3) {
            if (s0) ssum += __fdividef(1.f, 1.f + __expf(-x[k].x));
            if (s1) ssum += __fdividef(1.f, 1.f + __expf(-x[k].y));
            if (s2) ssum += __fdividef(1.f, 1.f + __expf(-x[k].z));
            if (s3) ssum += __fdividef(1.f, 1.f + __expf(-x[k].w));
        }
    }

    // Deterministic fixed-point conversion before reduction
    unsigned long long fsum = (unsigned long long)(ssum * FIXSCALE + 0.5f);

    // Block reduction (8 warps)
    __shared__ int                scnt[8];
    __shared__ unsigned long long ssh[8];
    #pragma unroll
    for (int off = 16; off > 0; off >>= 1) {
        cnt  += __shfl_down_sync(0xFFFFFFFFu, cnt,  off);
        fsum += __shfl_down_sync(0xFFFFFFFFu, fsum, off);
    }
    int wid  = threadIdx.x >> 5;
    int lane = threadIdx.x & 31;
    if (lane == 0) { scnt[wid] = cnt; ssh[wid] = fsum; }
    __syncthreads();
    if (threadIdx.x == 0) {
        int tc = 0; unsigned long long ts = 0ULL;
        #pragma unroll
        for (int w = 0; w < 8; w++) { tc += scnt[w]; ts += ssh[w]; }
        atomicAdd(&g_cnt[bq], tc);
        atomicAdd(&g_ssum[bq], ts);
    }
}

// ---------------------------------------------------------------------------
// Kernel 3: grid (S_, BQ_). Emit score/valid; re-zero the (rare) rows that
// have cls>=4 but cnt<50. Also converts fg_idxs -> global_ids float, spread
// across all blocks. No counter reset here (prep-lite owns it) -> no race.
// ---------------------------------------------------------------------------
__global__ __launch_bounds__(256)
void finalize_kernel(const int* __restrict__ fg_idxs,
                     float* __restrict__ out_masks,
                     float* __restrict__ out_scores,
                     float* __restrict__ out_valid,
                     float* __restrict__ out_gid)
{
    const int chunk = blockIdx.x;
    const int bq    = blockIdx.y;

    // gid convert: flatten block space over 200000 elements
    int gi = (bq * S_ + chunk) * 256 + threadIdx.x;
    if (gi < BN_) out_gid[gi] = (float)fg_idxs[gi];

    const int cls = g_cls_pred[bq];
    const int cnt = g_cnt[bq];
    const int v   = (cnt >= MIN_PTS_NUM) && (cls >= MIN_INST_CLS);

    if (chunk == 0 && threadIdx.x == 0) {
        out_valid[bq] = (float)v;
        float sum = (float)((double)g_ssum[bq] * (1.0 / 16777216.0));
        out_scores[bq] = v ? sum / (float)cnt : 0.f;
    }

    if (!v && cls >= MIN_INST_CLS) {   // rare: instance class but too few points
        float4* __restrict__ om = reinterpret_cast<float4*>(out_masks) +
                                  (size_t)bq * NV_ + (size_t)chunk * CHUNK_;
        const float4 z = make_float4(0.f, 0.f, 0.f, 0.f);
        #pragma unroll
        for (int k = 0; k < 5; k++) {
            int i = threadIdx.x + k * 256;
            if (i < CHUNK_) __stcs(&om[i], z);
        }
    }
}

// ---------------------------------------------------------------------------
extern "C" void kernel_launch(void* const* d_in, const int* in_sizes, int n_in,
                              void* d_out, int out_size)
{
    const float* mask_logits = (const float*)d_in[0];   // [B,Q,N]  fp32
    const float* cls_logits  = (const float*)d_in[1];   // [B,Q,C]  fp32
    const int*   seg_pred    = (const int*)d_in[2];     // [B,N]    int32
    const int*   fg_idxs     = (const int*)d_in[3];     // [B*N]    int32
    float* out = (float*)d_out;

    float* out_masks  = out;
    float* out_scores = out + OFF_SCORES;
    float* out_valid  = out + OFF_VALID;
    float* out_cls    = out + OFF_CLS;
    float* out_gid    = out + OFF_GID;

    dim3 grid2(S_, BQ_);
    prep_lite_kernel<<<2, 256>>>(cls_logits, out_cls);
    mask_chunk_kernel<<<grid2, 256>>>(mask_logits, seg_pred, out_masks);
    finalize_kernel<<<grid2, 256>>>(fg_idxs, out_masks, out_scores,
                                    out_valid, out_gid);
}